// round 1
// baseline (speedup 1.0000x reference)
#include <cuda_runtime.h>
#include <math.h>

#define F_IN 128
#define C3   192   // 3 * OUT, fused z|r|h feature block
#define OUT  64
#define NMAX 50048

// Scratch (no allocations allowed in kernel_launch)
__device__ float g_dinv[NMAX];
__device__ float g_xw [(size_t)NMAX * C3];
__device__ float g_agg[(size_t)NMAX * C3];

// ---------------------------------------------------------------- degree/norm
__global__ void k_deg_init(int n) {
    int i = blockIdx.x * blockDim.x + threadIdx.x;
    if (i < n) g_dinv[i] = 1.0f;              // self-loop weight 1
}

__global__ void k_deg_edges(const int* __restrict__ dst,
                            const float* __restrict__ w, int e) {
    int i = blockIdx.x * blockDim.x + threadIdx.x;
    if (i < e) atomicAdd(&g_dinv[dst[i]], w[i]);
}

__global__ void k_rsqrt(int n) {
    int i = blockIdx.x * blockDim.x + threadIdx.x;
    if (i < n) {
        float d = g_dinv[i];
        g_dinv[i] = (d > 0.0f) ? rsqrtf(d) : 0.0f;
    }
}

// ---------------------------------------------------------------- XW = x @ [Wz|Wr|Wh]
// Block: 64 rows x 192 cols, 256 threads, thread tile 4x12, K tiled by 32.
__global__ void k_xw(const float* __restrict__ x,
                     const float* __restrict__ Wz,
                     const float* __restrict__ Wr,
                     const float* __restrict__ Wh, int n) {
    __shared__ float xs[64 * 32];    // [r][kk]
    __shared__ float ws[32 * 192];   // [kk][j]
    const int tid = threadIdx.x;
    const int row0 = blockIdx.x * 64;
    const int tx = tid & 15, ty = tid >> 4;

    float acc[4][12];
#pragma unroll
    for (int r = 0; r < 4; r++)
#pragma unroll
        for (int c = 0; c < 12; c++) acc[r][c] = 0.0f;

    for (int k0 = 0; k0 < F_IN; k0 += 32) {
        for (int i = tid; i < 2048; i += 256) {
            int r = i >> 5, kk = i & 31;
            int row = row0 + r;
            xs[r * 32 + kk] = (row < n) ? x[(size_t)row * F_IN + k0 + kk] : 0.0f;
        }
        for (int i = tid; i < 6144; i += 256) {
            int kk = i / 192, j = i - kk * 192;
            const float* W = (j < 64) ? Wz : ((j < 128) ? Wr : Wh);
            int jj = j & 63;
            ws[kk * 192 + j] = W[(k0 + kk) * 64 + jj];
        }
        __syncthreads();

#pragma unroll 8
        for (int kk = 0; kk < 32; kk++) {
            float b[12];
            *(float4*)&b[0] = *(const float4*)&ws[kk * 192 + tx * 12];
            *(float4*)&b[4] = *(const float4*)&ws[kk * 192 + tx * 12 + 4];
            *(float4*)&b[8] = *(const float4*)&ws[kk * 192 + tx * 12 + 8];
#pragma unroll
            for (int r = 0; r < 4; r++) {
                float a = xs[(ty * 4 + r) * 32 + kk];
#pragma unroll
                for (int c = 0; c < 12; c++) acc[r][c] += a * b[c];
            }
        }
        __syncthreads();
    }

#pragma unroll
    for (int r = 0; r < 4; r++) {
        int row = row0 + ty * 4 + r;
        if (row < n) {
            float* dp = &g_xw[(size_t)row * C3 + tx * 12];
#pragma unroll
            for (int c = 0; c < 12; c++) dp[c] = acc[r][c];
        }
    }
}

// ---------------------------------------------------------------- self-loop init
__global__ void k_agg_init(int n) {
    int idx = blockIdx.x * blockDim.x + threadIdx.x;
    if (idx < n * C3) {
        int i = idx / C3;
        float di = g_dinv[i];
        g_agg[idx] = di * di * g_xw[idx];
    }
}

// ---------------------------------------------------------------- edge scatter
// one warp per edge (grid-stride); 6 strided float RED per lane
__global__ void k_scatter(const int* __restrict__ src,
                          const int* __restrict__ dst,
                          const float* __restrict__ w, int e) {
    int gw = (blockIdx.x * blockDim.x + threadIdx.x) >> 5;
    int lane = threadIdx.x & 31;
    int nw = (gridDim.x * blockDim.x) >> 5;
    for (int ed = gw; ed < e; ed += nw) {
        int s = src[ed], d = dst[ed];
        float nm = g_dinv[s] * w[ed] * g_dinv[d];
        const float* xr = &g_xw[(size_t)s * C3];
        float* ar = &g_agg[(size_t)d * C3];
#pragma unroll
        for (int t = 0; t < 6; t++) {
            int j = lane + t * 32;
            atomicAdd(ar + j, nm * xr[j]);
        }
    }
}

// ---------------------------------------------------------------- fused gates + GRU + output
// 64-node tile per block. All three L matrices + Agg/H tiles in dynamic smem.
// Thread (ty,tx) owns nodes r0..r0+3, cols c0..c0+3 across all gates.
__global__ void k_gates(const float* __restrict__ H,
                        const float* __restrict__ bz, const float* __restrict__ br,
                        const float* __restrict__ bh,
                        const float* __restrict__ Lz, const float* __restrict__ lbz,
                        const float* __restrict__ Lr, const float* __restrict__ lbr,
                        const float* __restrict__ Lh, const float* __restrict__ lbh,
                        const float* __restrict__ Wo, const float* __restrict__ bo,
                        float* __restrict__ out, int n) {
    extern __shared__ float sm[];
    float* sLz = sm;                 // 128*64
    float* sLr = sm + 8192;          // 128*64
    float* sLh = sm + 16384;         // 128*64
    float* sA  = sm + 24576;         // 64*192 (gcn outputs + biases)
    float* sH  = sA + 12288;         // 64*64
    float* sR  = sH + 4096;          // 64*64 (becomes H*R)

    const int tid = threadIdx.x;
    const int node0 = blockIdx.x * 64;

    for (int i = tid; i < 8192; i += 256) {
        sLz[i] = Lz[i]; sLr[i] = Lr[i]; sLh[i] = Lh[i];
    }
    for (int i = tid; i < 12288; i += 256) {
        int r = i / 192, j = i - r * 192;
        int node = node0 + r;
        float b = (j < 64) ? bz[j] : ((j < 128) ? br[j - 64] : bh[j - 128]);
        sA[i] = (node < n) ? g_agg[(size_t)node * C3 + j] + b : 0.0f;
    }
    for (int i = tid; i < 4096; i += 256) {
        int r = i >> 6;
        int node = node0 + r;
        sH[i] = (node < n) ? H[(size_t)node * OUT + (i & 63)] : 0.0f;
    }
    __syncthreads();

    const int tx = tid & 15, ty = tid >> 4;
    const int r0 = ty * 4, c0 = tx * 4;

    float zacc[4][4], racc[4][4];
#pragma unroll
    for (int cc = 0; cc < 4; cc++) {
        float vz = lbz[c0 + cc], vr = lbr[c0 + cc];
#pragma unroll
        for (int rr = 0; rr < 4; rr++) { zacc[rr][cc] = vz; racc[rr][cc] = vr; }
    }

#pragma unroll 4
    for (int k = 0; k < 64; k++) {
        float lz1[4], lz2[4], lr1[4], lr2[4];
        *(float4*)lz1 = *(const float4*)&sLz[k * 64 + c0];
        *(float4*)lz2 = *(const float4*)&sLz[(64 + k) * 64 + c0];
        *(float4*)lr1 = *(const float4*)&sLr[k * 64 + c0];
        *(float4*)lr2 = *(const float4*)&sLr[(64 + k) * 64 + c0];
#pragma unroll
        for (int rr = 0; rr < 4; rr++) {
            float az = sA[(r0 + rr) * 192 + k];
            float ag = sA[(r0 + rr) * 192 + 64 + k];
            float h  = sH[(r0 + rr) * 64 + k];
#pragma unroll
            for (int cc = 0; cc < 4; cc++) {
                zacc[rr][cc] += az * lz1[cc] + h * lz2[cc];
                racc[rr][cc] += ag * lr1[cc] + h * lr2[cc];
            }
        }
    }

    // activations; write H*R tile (each thread owns its own 16 entries)
#pragma unroll
    for (int rr = 0; rr < 4; rr++)
#pragma unroll
        for (int cc = 0; cc < 4; cc++) {
            zacc[rr][cc] = 1.0f / (1.0f + expf(-zacc[rr][cc]));
            float r_ = 1.0f / (1.0f + expf(-racc[rr][cc]));
            int idx = (r0 + rr) * 64 + c0 + cc;
            sR[idx] = r_ * sH[idx];
        }
    __syncthreads();

    float hacc[4][4];
#pragma unroll
    for (int cc = 0; cc < 4; cc++) {
        float vh = lbh[c0 + cc];
#pragma unroll
        for (int rr = 0; rr < 4; rr++) hacc[rr][cc] = vh;
    }

#pragma unroll 4
    for (int k = 0; k < 64; k++) {
        float lh1[4], lh2[4];
        *(float4*)lh1 = *(const float4*)&sLh[k * 64 + c0];
        *(float4*)lh2 = *(const float4*)&sLh[(64 + k) * 64 + c0];
#pragma unroll
        for (int rr = 0; rr < 4; rr++) {
            float ah = sA[(r0 + rr) * 192 + 128 + k];
            float hr = sR[(r0 + rr) * 64 + k];
#pragma unroll
            for (int cc = 0; cc < 4; cc++)
                hacc[rr][cc] += ah * lh1[cc] + hr * lh2[cc];
        }
    }

    float wov[4];
#pragma unroll
    for (int cc = 0; cc < 4; cc++) wov[cc] = Wo[c0 + cc];
    float yp[4] = {0.f, 0.f, 0.f, 0.f};

#pragma unroll
    for (int rr = 0; rr < 4; rr++) {
        int node = node0 + r0 + rr;
#pragma unroll
        for (int cc = 0; cc < 4; cc++) {
            float ht = tanhf(hacc[rr][cc]);
            float z = zacc[rr][cc];
            float h = sH[(r0 + rr) * 64 + c0 + cc];
            float hn = z * h + (1.0f - z) * ht;
            if (node < n) out[(size_t)n + (size_t)node * OUT + c0 + cc] = hn;
            yp[rr] += fmaxf(hn, 0.0f) * wov[cc];
        }
    }
    // reduce y partials across the 16 tx lanes (xor stays within half-warp ty group)
#pragma unroll
    for (int off = 8; off > 0; off >>= 1)
#pragma unroll
        for (int rr = 0; rr < 4; rr++)
            yp[rr] += __shfl_xor_sync(0xffffffffu, yp[rr], off);
    if (tx == 0) {
        float b0 = bo[0];
#pragma unroll
        for (int rr = 0; rr < 4; rr++) {
            int node = node0 + r0 + rr;
            if (node < n) out[node] = yp[rr] + b0;
        }
    }
}

// ---------------------------------------------------------------- launch
extern "C" void kernel_launch(void* const* d_in, const int* in_sizes, int n_in,
                              void* d_out, int out_size) {
    const float* x   = (const float*)d_in[0];
    const int*   ei  = (const int*)d_in[1];
    const float* ew  = (const float*)d_in[2];
    const float* H   = (const float*)d_in[3];
    // d_in[4] = c (unused)
    const float* Wz  = (const float*)d_in[5];
    const float* bz  = (const float*)d_in[6];
    const float* Wr  = (const float*)d_in[7];
    const float* br  = (const float*)d_in[8];
    const float* Wh  = (const float*)d_in[9];
    const float* bh  = (const float*)d_in[10];
    const float* Lz  = (const float*)d_in[11];
    const float* lbz = (const float*)d_in[12];
    const float* Lr  = (const float*)d_in[13];
    const float* lbr = (const float*)d_in[14];
    const float* Lh  = (const float*)d_in[15];
    const float* lbh = (const float*)d_in[16];
    const float* Wo  = (const float*)d_in[17];
    const float* bo  = (const float*)d_in[18];
    float* out = (float*)d_out;

    int n = in_sizes[0] / F_IN;
    int e = in_sizes[2];
    const int* src = ei;
    const int* dst = ei + e;

    k_deg_init <<<(n + 255) / 256, 256>>>(n);
    k_deg_edges<<<(e + 255) / 256, 256>>>(dst, ew, e);
    k_rsqrt    <<<(n + 255) / 256, 256>>>(n);
    k_xw       <<<(n + 63) / 64, 256>>>(x, Wz, Wr, Wh, n);
    k_agg_init <<<(n * C3 + 255) / 256, 256>>>(n);
    k_scatter  <<<2368, 256>>>(src, dst, ew, e);

    cudaFuncSetAttribute(k_gates, cudaFuncAttributeMaxDynamicSharedMemorySize, 180224);
    k_gates<<<(n + 63) / 64, 256, 180224>>>(H, bz, br, bh, Lz, lbz, Lr, lbr,
                                            Lh, lbh, Wo, bo, out, n);
}